// round 1
// baseline (speedup 1.0000x reference)
#include <cuda_runtime.h>

// Problem geometry: predict/target [2, 4, 64, 256, 256] fp32
// -> 512 slices of 65536 elements each.
#define HW        65536
#define NSLICES   512
#define SLICE_D   64
#define NPAIRS    8        // B*O = 2*4
#define TPB       512

__device__ float g_dice[NSLICES];
__device__ float g_valid[NSLICES];

__device__ __forceinline__ float sigmoidf_fast(float x) {
    return 1.0f / (1.0f + __expf(-x));
}

__global__ __launch_bounds__(TPB, 2)
void dice_slice_kernel(const float* __restrict__ predict,
                       const float* __restrict__ target) {
    const int s   = blockIdx.x;
    const int tid = threadIdx.x;

    const float4* __restrict__ p4 =
        reinterpret_cast<const float4*>(predict + (size_t)s * HW);
    const float4* __restrict__ t4 =
        reinterpret_cast<const float4*>(target + (size_t)s * HW);

    float num = 0.0f, sp = 0.0f, st = 0.0f;

    // 65536/4 = 16384 float4 per slice; 512 threads -> 32 iters/thread.
    #pragma unroll 8
    for (int i = tid; i < HW / 4; i += TPB) {
        float4 a = p4[i];
        float4 b = t4[i];
        float s0 = sigmoidf_fast(a.x);
        float s1 = sigmoidf_fast(a.y);
        float s2 = sigmoidf_fast(a.z);
        float s3 = sigmoidf_fast(a.w);
        num += s0 * b.x + s1 * b.y + s2 * b.z + s3 * b.w;
        sp  += s0 + s1 + s2 + s3;
        st  += b.x + b.y + b.z + b.w;
    }

    // Warp reduce the three accumulators.
    #pragma unroll
    for (int off = 16; off > 0; off >>= 1) {
        num += __shfl_down_sync(0xffffffffu, num, off);
        sp  += __shfl_down_sync(0xffffffffu, sp,  off);
        st  += __shfl_down_sync(0xffffffffu, st,  off);
    }

    __shared__ float s_num[TPB / 32];
    __shared__ float s_sp [TPB / 32];
    __shared__ float s_st [TPB / 32];

    const int lane = tid & 31;
    const int wid  = tid >> 5;
    if (lane == 0) {
        s_num[wid] = num;
        s_sp [wid] = sp;
        s_st [wid] = st;
    }
    __syncthreads();

    if (wid == 0) {
        num = (lane < TPB / 32) ? s_num[lane] : 0.0f;
        sp  = (lane < TPB / 32) ? s_sp [lane] : 0.0f;
        st  = (lane < TPB / 32) ? s_st [lane] : 0.0f;
        #pragma unroll
        for (int off = 8; off > 0; off >>= 1) {
            num += __shfl_down_sync(0xffffffffu, num, off);
            sp  += __shfl_down_sync(0xffffffffu, sp,  off);
            st  += __shfl_down_sync(0xffffffffu, st,  off);
        }
        if (lane == 0) {
            float dice = 1.0f - 2.0f * num / (sp + st + 1.0f);
            g_dice[s]  = dice;
            // valid iff first element of the flattened [D, H*W] slice != -1
            g_valid[s] = (target[(size_t)s * HW] != -1.0f) ? 1.0f : 0.0f;
        }
    }
}

__global__ __launch_bounds__(NSLICES)
void dice_finalize_kernel(float* __restrict__ out) {
    __shared__ float g_sum[NPAIRS];
    __shared__ float g_cnt[NPAIRS];

    const int tid = threadIdx.x;
    if (tid < NPAIRS) { g_sum[tid] = 0.0f; g_cnt[tid] = 0.0f; }
    __syncthreads();

    float d = g_dice[tid];
    float v = g_valid[tid];
    const int pair = tid / SLICE_D;
    atomicAdd(&g_sum[pair], d * v);
    atomicAdd(&g_cnt[pair], v);
    __syncthreads();

    if (tid == 0) {
        float acc = 0.0f;
        #pragma unroll
        for (int i = 0; i < NPAIRS; i++)
            acc += g_sum[i] / g_cnt[i];
        out[0] = acc / (float)NPAIRS;
    }
}

extern "C" void kernel_launch(void* const* d_in, const int* in_sizes, int n_in,
                              void* d_out, int out_size) {
    const float* predict = (const float*)d_in[0];
    const float* target  = (const float*)d_in[1];
    float* out = (float*)d_out;

    dice_slice_kernel<<<NSLICES, TPB>>>(predict, target);
    dice_finalize_kernel<<<1, NSLICES>>>(out);
}

// round 2
// speedup vs baseline: 1.1655x; 1.1655x over previous
#include <cuda_runtime.h>

// predict/target: [2, 4, 64, 256, 256] fp32 -> 512 slices of 65536 elems.
#define HW              65536
#define NSLICES         512
#define SLICE_D         64
#define NPAIRS          8
#define TPB             256
#define CTAS_PER_SLICE  2
#define GRID            (NSLICES * CTAS_PER_SLICE)   // 1024
#define CHUNK_F4        (HW / 4 / CTAS_PER_SLICE)    // 8192 float4 per CTA

// Persistent device state (zero-initialized; reset by the finalizing CTA so
// the kernel stays graph-replayable and deterministic).
__device__ float        g_num[NSLICES];
__device__ float        g_sp [NSLICES];
__device__ float        g_st [NSLICES];
__device__ unsigned int g_done;

// sigmoid(x) = 0.5 * tanh(0.5 x) + 0.5  (tanh.approx.f32: 1 MUFU op)
__device__ __forceinline__ float fast_sigmoid(float x) {
    float t;
    asm("tanh.approx.f32 %0, %1;" : "=f"(t) : "f"(x * 0.5f));
    return fmaf(0.5f, t, 0.5f);
}

__global__ __launch_bounds__(TPB, 7)
void dice_fused_kernel(const float* __restrict__ predict,
                       const float* __restrict__ target,
                       float* __restrict__ out) {
    const int cta  = blockIdx.x;
    const int s    = cta >> 1;         // slice index
    const int half = cta & 1;          // which half of the slice
    const int tid  = threadIdx.x;

    const size_t base = (size_t)s * (HW / 4) + (size_t)half * CHUNK_F4;
    const float4* __restrict__ p4 = reinterpret_cast<const float4*>(predict) + base;
    const float4* __restrict__ t4 = reinterpret_cast<const float4*>(target)  + base;

    float num = 0.0f, sp = 0.0f, st = 0.0f;

    #pragma unroll 4
    for (int i = tid; i < CHUNK_F4; i += TPB) {
        float4 a = p4[i];
        float4 b = t4[i];
        float s0 = fast_sigmoid(a.x);
        float s1 = fast_sigmoid(a.y);
        float s2 = fast_sigmoid(a.z);
        float s3 = fast_sigmoid(a.w);
        num += s0 * b.x + s1 * b.y + s2 * b.z + s3 * b.w;
        sp  += s0 + s1 + s2 + s3;
        st  += b.x + b.y + b.z + b.w;
    }

    // Warp reduce.
    #pragma unroll
    for (int off = 16; off > 0; off >>= 1) {
        num += __shfl_down_sync(0xffffffffu, num, off);
        sp  += __shfl_down_sync(0xffffffffu, sp,  off);
        st  += __shfl_down_sync(0xffffffffu, st,  off);
    }

    __shared__ float s_num[TPB / 32];
    __shared__ float s_sp [TPB / 32];
    __shared__ float s_st [TPB / 32];
    __shared__ bool  s_last;

    const int lane = tid & 31;
    const int wid  = tid >> 5;
    if (lane == 0) { s_num[wid] = num; s_sp[wid] = sp; s_st[wid] = st; }
    __syncthreads();

    if (tid == 0) {
        float n = 0.0f, a = 0.0f, b = 0.0f;
        #pragma unroll
        for (int w = 0; w < TPB / 32; w++) { n += s_num[w]; a += s_sp[w]; b += s_st[w]; }
        atomicAdd(&g_num[s], n);
        atomicAdd(&g_sp [s], a);
        atomicAdd(&g_st [s], b);
        __threadfence();
        unsigned int d = atomicAdd(&g_done, 1u);
        s_last = (d == GRID - 1);
    }
    __syncthreads();

    // ---- Fused finalize: last CTA reduces all 512 slices ----
    if (s_last) {
        __threadfence();  // acquire: all producer atomics are visible

        __shared__ float p_sum[NPAIRS];
        __shared__ float p_cnt[NPAIRS];
        if (tid < NPAIRS) { p_sum[tid] = 0.0f; p_cnt[tid] = 0.0f; }
        __syncthreads();

        for (int i = tid; i < NSLICES; i += TPB) {
            float n = g_num[i];
            float a = g_sp [i];
            float b = g_st [i];
            float dice = 1.0f - 2.0f * n / (a + b + 1.0f);
            float v = (target[(size_t)i * HW] != -1.0f) ? 1.0f : 0.0f;
            atomicAdd(&p_sum[i / SLICE_D], dice * v);
            atomicAdd(&p_cnt[i / SLICE_D], v);
            // Reset state for the next graph replay.
            g_num[i] = 0.0f; g_sp[i] = 0.0f; g_st[i] = 0.0f;
        }
        __syncthreads();

        if (tid == 0) {
            float acc = 0.0f;
            #pragma unroll
            for (int i = 0; i < NPAIRS; i++) acc += p_sum[i] / p_cnt[i];
            out[0] = acc * (1.0f / (float)NPAIRS);
            g_done = 0u;
        }
    }
}

extern "C" void kernel_launch(void* const* d_in, const int* in_sizes, int n_in,
                              void* d_out, int out_size) {
    const float* predict = (const float*)d_in[0];
    const float* target  = (const float*)d_in[1];
    float* out = (float*)d_out;

    dice_fused_kernel<<<GRID, TPB>>>(predict, target, out);
}